// round 8
// baseline (speedup 1.0000x reference)
#include <cuda_runtime.h>
#include <cstdint>

// VolSDF volume renderer — cp.async.bulk double-buffered SMEM pipeline.
// Inputs: distance [M,128,1] f32, color [M,128,3] f32, depth_values [M,128] f32
// Output: out_color [M,3] f32 followed by geometry [M,3] f32 (zeros).
//
// Numerics (validated rel_err 8e-8): reference float32 cumsum is a BLOCKED
// scan (chunk=16); sample 127 (FAR_DELTA=1e10 sentinel) uses
//   cs127 = fl( S[0:112) + fl( S[112:127) + sd127 ) ).
// Per-sample: inc = fl(run+sd); T = exp(-(inc-sd)); w = T*(1-exp(-sd)).
//
// Data path: tiles of 8 rays (20 KB) staged GMEM->SMEM via cp.async.bulk with
// mbarrier complete_tx, depth-2 pipeline. Registers no longer hold in-flight
// load data, so the async queue (not the RF) bounds outstanding DRAM requests.

#define FAR_DELTA_ 1e10f
#define TILE_RAYS 8

// ---------------- PTX helpers ----------------
__device__ __forceinline__ uint32_t smem_u32(const void* p) {
    uint32_t a;
    asm("{ .reg .u64 t; cvta.to.shared.u64 t, %1; cvt.u32.u64 %0, t; }"
        : "=r"(a) : "l"(p));
    return a;
}

__device__ __forceinline__ void mbar_init(uint32_t mbar, uint32_t count) {
    asm volatile("mbarrier.init.shared.b64 [%0], %1;" :: "r"(mbar), "r"(count) : "memory");
}

__device__ __forceinline__ void mbar_expect_tx(uint32_t mbar, uint32_t bytes) {
    asm volatile("mbarrier.arrive.expect_tx.shared.b64 _, [%0], %1;"
                 :: "r"(mbar), "r"(bytes) : "memory");
}

__device__ __forceinline__ void bulk_g2s(uint32_t dst, const void* src,
                                         uint32_t bytes, uint32_t mbar) {
    asm volatile(
        "cp.async.bulk.shared::cluster.global.mbarrier::complete_tx::bytes "
        "[%0], [%1], %2, [%3];"
        :: "r"(dst), "l"(src), "r"(bytes), "r"(mbar) : "memory");
}

__device__ __forceinline__ void mbar_wait_parity(uint32_t mbar, uint32_t parity) {
    asm volatile(
        "{\n\t"
        ".reg .pred P;\n\t"
        "WAIT_%=: \n\t"
        "mbarrier.try_wait.parity.acquire.cta.shared::cta.b64 P, [%0], %1, 0x989680;\n\t"
        "@P bra.uni DONE_%=;\n\t"
        "bra.uni WAIT_%=;\n\t"
        "DONE_%=: \n\t"
        "}"
        :: "r"(mbar), "r"(parity) : "memory");
}

// ---------------- math (validated) ----------------
__device__ __forceinline__ float sdf_density(float d) {
    float s = -d;
    float a = fabsf(s) / 0.05f;
    float e = expf(-a);
    return (s <= 0.0f) ? __fmul_rn(10.0f, __fmul_rn(0.5f, e))
                       : __fmul_rn(10.0f, __fsub_rn(1.0f, __fmul_rn(0.5f, e)));
}

__device__ __forceinline__ void render_step(float& run, float sd,
                                            float cr, float cg, float cb,
                                            float& r, float& g, float& b) {
    float inc = __fadd_rn(run, sd);
    float T   = expf(-__fsub_rn(inc, sd));
    float w   = T * (1.0f - expf(-sd));
    run = inc;
    r += w * cr; g += w * cg; b += w * cb;
}

// Full per-ray pipeline from SMEM-resident tile data.
__device__ __forceinline__ void process_ray(
    int lane, long long ray, int M,
    const float* __restrict__ sdist,   // 128 floats, this ray
    const float* __restrict__ sdep,    // 128 floats
    const float* __restrict__ scol,    // 384 floats
    float* __restrict__ out)
{
    const unsigned FULL = 0xffffffffu;

    const float4 d4 = *reinterpret_cast<const float4*>(sdist + lane * 4);
    const float4 z4 = *reinterpret_cast<const float4*>(sdep  + lane * 4);
    const float4 c0 = *reinterpret_cast<const float4*>(scol + lane * 12 + 0);
    const float4 c1 = *reinterpret_cast<const float4*>(scol + lane * 12 + 4);
    const float4 c2 = *reinterpret_cast<const float4*>(scol + lane * 12 + 8);

    if (lane == 1) {  // geometry zeros for this ray
        const long long gb = (long long)M * 3 + ray * 3;
        out[gb + 0] = 0.0f; out[gb + 1] = 0.0f; out[gb + 2] = 0.0f;
    }

    const float z_next = __shfl_down_sync(FULL, z4.x, 1);

    const float del0 = __fsub_rn(z4.y, z4.x);
    const float del1 = __fsub_rn(z4.z, z4.y);
    const float del2 = __fsub_rn(z4.w, z4.z);
    const float del3 = (lane == 31) ? FAR_DELTA_ : __fsub_rn(z_next, z4.w);

    const float sd0 = __fmul_rn(sdf_density(d4.x), del0);
    const float sd1 = __fmul_rn(sdf_density(d4.y), del1);
    const float sd2 = __fmul_rn(sdf_density(d4.z), del2);
    const float sd3 = __fmul_rn(sdf_density(d4.w), del3);

    const float lsum = __fadd_rn(__fadd_rn(__fadd_rn(sd0, sd1), sd2), sd3);

    // warp inclusive scan (Kogge-Stone)
    float x = lsum;
    #pragma unroll
    for (int off = 1; off < 32; off <<= 1) {
        float y = __shfl_up_sync(FULL, x, off);
        if (lane >= off) x += y;
    }
    float run = __shfl_up_sync(FULL, x, 1);
    if (lane == 0) run = 0.0f;

    const float x27 = __shfl_sync(FULL, x, 27);   // S[0:112)
    const float x30 = __shfl_sync(FULL, x, 30);   // S[0:124)

    float r = 0.0f, g = 0.0f, b = 0.0f;
    render_step(run, sd0, c0.x, c0.y, c0.z, r, g, b);
    render_step(run, sd1, c0.w, c1.x, c1.y, r, g, b);
    render_step(run, sd2, c1.z, c1.w, c2.x, r, g, b);

    if (lane != 31) {
        render_step(run, sd3, c2.y, c2.z, c2.w, r, g, b);
    } else {
        // Blocked scan, chunk 16: local chunk = samples [112,128).
        const float Lloc  = __fadd_rn(__fsub_rn(x30, x27),
                                      __fadd_rn(__fadd_rn(sd0, sd1), sd2));
        const float local = __fadd_rn(Lloc, sd3);
        const float cs    = __fadd_rn(x27, local);
        const float q     = __fsub_rn(cs, sd3);
        const float T     = expf(-q);
        const float w     = T * (1.0f - expf(-sd3));
        r += w * c2.y; g += w * c2.z; b += w * c2.w;
    }

    #pragma unroll
    for (int off = 16; off > 0; off >>= 1) {
        r += __shfl_xor_sync(FULL, r, off);
        g += __shfl_xor_sync(FULL, g, off);
        b += __shfl_xor_sync(FULL, b, off);
    }

    if (lane == 0) {
        out[ray * 3 + 0] = r;
        out[ray * 3 + 1] = g;
        out[ray * 3 + 2] = b;
    }
}

// ---------------- kernel ----------------
__global__ void __launch_bounds__(256) volsdf_render_kernel(
    const float* __restrict__ dist,
    const float* __restrict__ color,
    const float* __restrict__ depth,
    float* __restrict__ out,
    int M)
{
    __shared__ __align__(16) float s_dist[2][TILE_RAYS * 128];
    __shared__ __align__(16) float s_dep [2][TILE_RAYS * 128];
    __shared__ __align__(16) float s_col [2][TILE_RAYS * 384];
    __shared__ __align__(8)  unsigned long long s_mbar[2];

    const int tid  = threadIdx.x;
    const int wid  = tid >> 5;
    const int lane = tid & 31;

    const int ntiles = (M + TILE_RAYS - 1) / TILE_RAYS;

    if (tid == 0) {
        mbar_init(smem_u32(&s_mbar[0]), 1);
        mbar_init(smem_u32(&s_mbar[1]), 1);
    }
    __syncthreads();

    // issue one tile's 3 bulk copies into buffer `buf`
    auto issue = [&](long long tl, int bi) {
        if (tid == 0) {
            const int nr = min(TILE_RAYS, M - (int)(tl * TILE_RAYS));
            const uint32_t bD = (uint32_t)nr * 512u;    // dist bytes
            const uint32_t bC = (uint32_t)nr * 1536u;   // color bytes
            const uint32_t mb = smem_u32(&s_mbar[bi]);
            mbar_expect_tx(mb, bD * 2u + bC);
            bulk_g2s(smem_u32(&s_dist[bi][0]), dist  + tl * (TILE_RAYS * 128), bD, mb);
            bulk_g2s(smem_u32(&s_dep [bi][0]), depth + tl * (TILE_RAYS * 128), bD, mb);
            bulk_g2s(smem_u32(&s_col [bi][0]), color + tl * (TILE_RAYS * 384), bC, mb);
        }
    };

    long long tile  = blockIdx.x;
    const long long stride = gridDim.x;

    int phase[2] = {0, 0};
    int buf = 0;

    if (tile < ntiles) issue(tile, 0);

    for (; tile < ntiles; tile += stride) {
        const long long nxt = tile + stride;
        if (nxt < ntiles) issue(nxt, buf ^ 1);

        mbar_wait_parity(smem_u32(&s_mbar[buf]), phase[buf]);
        phase[buf] ^= 1;

        const int nr = min(TILE_RAYS, M - (int)(tile * TILE_RAYS));
        if (wid < nr) {
            process_ray(lane, tile * TILE_RAYS + wid, M,
                        &s_dist[buf][wid * 128],
                        &s_dep [buf][wid * 128],
                        &s_col [buf][wid * 384],
                        out);
        }
        __syncthreads();   // all warps done reading buf before it is refilled
        buf ^= 1;
    }
}

extern "C" void kernel_launch(void* const* d_in, const int* in_sizes, int n_in,
                              void* d_out, int out_size) {
    const float* dist  = (const float*)d_in[0];   // [M,128,1]
    const float* color = (const float*)d_in[1];   // [M,128,3]
    const float* depth = (const float*)d_in[2];   // [M,128]

    const int M = in_sizes[2] / 128;
    float* out = (float*)d_out;

    // Kernel writes out_color and geometry zeros; memset only any tail beyond.
    const long long expected = (long long)M * 6;
    if ((long long)out_size > expected) {
        cudaMemsetAsync(out + expected, 0,
                        ((long long)out_size - expected) * sizeof(float), 0);
    }

    const int ntiles = (M + TILE_RAYS - 1) / TILE_RAYS;   // 8192 for M=65536
    int blocks = (ntiles + 3) / 4;                        // ~4 tiles per CTA
    if (blocks < 1) blocks = 1;
    if (blocks > ntiles) blocks = ntiles;
    volsdf_render_kernel<<<blocks, 256>>>(dist, color, depth, out, M);
}

// round 9
// speedup vs baseline: 1.1534x; 1.1534x over previous
#include <cuda_runtime.h>

// VolSDF volume renderer.
// Inputs: distance [M,128,1] f32, color [M,128,3] f32, depth_values [M,128] f32
// Output: out_color [M,3] f32 followed by geometry [M,3] f32 (zeros).
//
// One warp per ray; lane l owns samples [4l, 4l+4). R5's kernel body (best
// measured: 39 regs, DRAM 74.9%) + in-kernel geometry zeros (no memset node).
//
// Numerics (validated rel_err 8e-8): the reference float32 cumsum is a
// BLOCKED scan (chunk=16); sample 127 (FAR_DELTA=1e10 sentinel) uses
//   cs127 = fl( S[0:112) + fl( S[112:127) + sd127 ) ).
// Per-sample: inc = fl(run+sd); T = exp(-(inc-sd)); w = T*(1-exp(-sd)).

#define FAR_DELTA_ 1e10f

__device__ __forceinline__ float sdf_density(float d) {
    float s = -d;
    float a = fabsf(s) / 0.05f;
    float e = expf(-a);
    return (s <= 0.0f) ? __fmul_rn(10.0f, __fmul_rn(0.5f, e))
                       : __fmul_rn(10.0f, __fsub_rn(1.0f, __fmul_rn(0.5f, e)));
}

// One render step with reference f32 rounding:
//   inc = fl(run + sd); T = exp(-(inc - sd)); w = T*(1-exp(-sd)); run = inc
__device__ __forceinline__ void render_step(float& run, float sd,
                                            float cr, float cg, float cb,
                                            float& r, float& g, float& b) {
    float inc = __fadd_rn(run, sd);
    float T   = expf(-__fsub_rn(inc, sd));
    float w   = T * (1.0f - expf(-sd));
    run = inc;
    r += w * cr; g += w * cg; b += w * cb;
}

__global__ void __launch_bounds__(256) volsdf_render_kernel(
    const float* __restrict__ dist,
    const float* __restrict__ color,
    const float* __restrict__ depth,
    float* __restrict__ out,
    int M)
{
    const int gtid = blockIdx.x * blockDim.x + threadIdx.x;
    const int ray  = gtid >> 5;
    const int lane = gtid & 31;
    if (ray >= M) return;

    const unsigned FULL = 0xffffffffu;
    const long long base = (long long)ray * 128;

    // ---- coalesced vector loads: 4 samples per lane, 5 LDG.128 front-batched
    const float4 d4 = *reinterpret_cast<const float4*>(dist  + base + lane * 4);
    const float4 z4 = *reinterpret_cast<const float4*>(depth + base + lane * 4);

    const long long cbase = base * 3 + (long long)lane * 12;
    const float4 c0 = *reinterpret_cast<const float4*>(color + cbase + 0);
    const float4 c1 = *reinterpret_cast<const float4*>(color + cbase + 4);
    const float4 c2 = *reinterpret_cast<const float4*>(color + cbase + 8);

    // geometry output zeros, overlapped with the in-flight loads
    if (lane == 1) {
        const long long gb = (long long)M * 3 + (long long)ray * 3;
        out[gb + 0] = 0.0f; out[gb + 1] = 0.0f; out[gb + 2] = 0.0f;
    }

    // next lane's first depth (delta for this lane's last sample)
    const float z_next = __shfl_down_sync(FULL, z4.x, 1);

    const float del0 = __fsub_rn(z4.y, z4.x);
    const float del1 = __fsub_rn(z4.z, z4.y);
    const float del2 = __fsub_rn(z4.w, z4.z);
    const float del3 = (lane == 31) ? FAR_DELTA_ : __fsub_rn(z_next, z4.w);

    const float sd0 = __fmul_rn(sdf_density(d4.x), del0);
    const float sd1 = __fmul_rn(sdf_density(d4.y), del1);
    const float sd2 = __fmul_rn(sdf_density(d4.z), del2);
    const float sd3 = __fmul_rn(sdf_density(d4.w), del3);

    const float lsum = __fadd_rn(__fadd_rn(__fadd_rn(sd0, sd1), sd2), sd3);

    // warp inclusive scan of per-lane sums (Kogge-Stone)
    float x = lsum;
    #pragma unroll
    for (int off = 1; off < 32; off <<= 1) {
        float y = __shfl_up_sync(FULL, x, off);
        if (lane >= off) x += y;
    }
    // exclusive prefix via shfl (no subtraction: lane 31's lsum is ~1e11)
    float run = __shfl_up_sync(FULL, x, 1);
    if (lane == 0) run = 0.0f;

    // snapshots for the sample-127 blocked-scan combine (uniform execution)
    const float x27 = __shfl_sync(FULL, x, 27);   // S[0:112)
    const float x30 = __shfl_sync(FULL, x, 30);   // S[0:124)

    float r = 0.0f, g = 0.0f, b = 0.0f;
    render_step(run, sd0, c0.x, c0.y, c0.z, r, g, b);
    render_step(run, sd1, c0.w, c1.x, c1.y, r, g, b);
    render_step(run, sd2, c1.z, c1.w, c2.x, r, g, b);

    if (lane != 31) {
        render_step(run, sd3, c2.y, c2.z, c2.w, r, g, b);
    } else {
        // Blocked scan, chunk 16: local chunk covers samples [112,128).
        const float Lloc  = __fadd_rn(__fsub_rn(x30, x27),
                                      __fadd_rn(__fadd_rn(sd0, sd1), sd2));
        const float local = __fadd_rn(Lloc, sd3);
        const float cs    = __fadd_rn(x27, local);
        const float q     = __fsub_rn(cs, sd3);
        const float T     = expf(-q);
        const float w     = T * (1.0f - expf(-sd3));
        r += w * c2.y; g += w * c2.z; b += w * c2.w;
    }

    // warp reduction of RGB
    #pragma unroll
    for (int off = 16; off > 0; off >>= 1) {
        r += __shfl_xor_sync(FULL, r, off);
        g += __shfl_xor_sync(FULL, g, off);
        b += __shfl_xor_sync(FULL, b, off);
    }

    if (lane == 0) {
        const long long ob = (long long)ray * 3;
        out[ob + 0] = r;
        out[ob + 1] = g;
        out[ob + 2] = b;
    }
}

extern "C" void kernel_launch(void* const* d_in, const int* in_sizes, int n_in,
                              void* d_out, int out_size) {
    const float* dist  = (const float*)d_in[0];   // [M,128,1]
    const float* color = (const float*)d_in[1];   // [M,128,3]
    const float* depth = (const float*)d_in[2];   // [M,128]

    const int M = in_sizes[2] / 128;
    float* out = (float*)d_out;

    // Kernel writes out_color and geometry zeros; memset only any tail beyond.
    const long long expected = (long long)M * 6;
    if ((long long)out_size > expected) {
        cudaMemsetAsync(out + expected, 0,
                        ((long long)out_size - expected) * sizeof(float), 0);
    }

    const int threads = 256;              // 8 warps -> 8 rays per block
    const int blocks  = (M + 7) / 8;
    volsdf_render_kernel<<<blocks, threads>>>(dist, color, depth, out, M);
}

// round 10
// speedup vs baseline: 1.1874x; 1.0294x over previous
#include <cuda_runtime.h>

// VolSDF volume renderer.
// Inputs: distance [M,128,1] f32, color [M,128,3] f32, depth_values [M,128] f32
// Output: out_color [M,3] f32 followed by geometry [M,3] f32 (zeros).
//
// One warp per ray; lane l owns samples [4l, 4l+4). R6 body (harness-best:
// ldcs streaming loads, 32-reg codegen, in-kernel geometry zeros) with the
// occupancy ceiling raised to 100% (512-thread blocks, min 4 blocks/SM):
// at natural DVFS clocks DRAM latency in cycles is ~1.8x the locked-clock
// value, so resident-warp count—not per-warp ILP—is the binding resource.
//
// Numerics (validated rel_err 8e-8): the reference float32 cumsum is a
// BLOCKED scan (chunk=16); sample 127 (FAR_DELTA=1e10 sentinel) uses
//   cs127 = fl( S[0:112) + fl( S[112:127) + sd127 ) ).
// Per-sample: inc = fl(run+sd); T = exp(-(inc-sd)); w = T*(1-exp(-sd)).

#define FAR_DELTA_ 1e10f

__device__ __forceinline__ float sdf_density(float d) {
    float s = -d;
    float a = fabsf(s) / 0.05f;
    float e = expf(-a);
    return (s <= 0.0f) ? __fmul_rn(10.0f, __fmul_rn(0.5f, e))
                       : __fmul_rn(10.0f, __fsub_rn(1.0f, __fmul_rn(0.5f, e)));
}

// One render step with reference f32 rounding:
//   inc = fl(run + sd); T = exp(-(inc - sd)); w = T*(1-exp(-sd)); run = inc
__device__ __forceinline__ void render_step(float& run, float sd,
                                            float cr, float cg, float cb,
                                            float& r, float& g, float& b) {
    float inc = __fadd_rn(run, sd);
    float T   = expf(-__fsub_rn(inc, sd));
    float w   = T * (1.0f - expf(-sd));
    run = inc;
    r += w * cr; g += w * cg; b += w * cb;
}

__device__ __forceinline__ float4 ldcs4(const float* p) {
    return __ldcs(reinterpret_cast<const float4*>(p));
}

__global__ void __launch_bounds__(512, 4) volsdf_render_kernel(
    const float* __restrict__ dist,
    const float* __restrict__ color,
    const float* __restrict__ depth,
    float* __restrict__ out,
    int M)
{
    const int gtid = blockIdx.x * blockDim.x + threadIdx.x;
    const int ray  = gtid >> 5;
    const int lane = gtid & 31;
    if (ray >= M) return;

    const unsigned FULL = 0xffffffffu;
    const long long base = (long long)ray * 128;

    // ---- coalesced streaming vector loads: 4 samples per lane ----
    const float4 d4 = ldcs4(dist  + base + lane * 4);
    const float4 z4 = ldcs4(depth + base + lane * 4);

    const long long cbase = base * 3 + (long long)lane * 12;
    const float4 c0 = ldcs4(color + cbase + 0);
    const float4 c1 = ldcs4(color + cbase + 4);
    const float4 c2 = ldcs4(color + cbase + 8);

    // geometry output zeros, overlapped with in-flight loads
    if (lane == 1) {
        const long long gb = (long long)M * 3 + (long long)ray * 3;
        out[gb + 0] = 0.0f; out[gb + 1] = 0.0f; out[gb + 2] = 0.0f;
    }

    // next lane's first depth (delta for this lane's last sample)
    const float z_next = __shfl_down_sync(FULL, z4.x, 1);

    const float del0 = __fsub_rn(z4.y, z4.x);
    const float del1 = __fsub_rn(z4.z, z4.y);
    const float del2 = __fsub_rn(z4.w, z4.z);
    const float del3 = (lane == 31) ? FAR_DELTA_ : __fsub_rn(z_next, z4.w);

    const float sd0 = __fmul_rn(sdf_density(d4.x), del0);
    const float sd1 = __fmul_rn(sdf_density(d4.y), del1);
    const float sd2 = __fmul_rn(sdf_density(d4.z), del2);
    const float sd3 = __fmul_rn(sdf_density(d4.w), del3);

    const float lsum = __fadd_rn(__fadd_rn(__fadd_rn(sd0, sd1), sd2), sd3);

    // warp inclusive scan of per-lane sums (Kogge-Stone)
    float x = lsum;
    #pragma unroll
    for (int off = 1; off < 32; off <<= 1) {
        float y = __shfl_up_sync(FULL, x, off);
        if (lane >= off) x += y;
    }
    // exclusive prefix via shfl (no subtraction: lane 31's lsum is ~1e11)
    float run = __shfl_up_sync(FULL, x, 1);
    if (lane == 0) run = 0.0f;

    // snapshots for the sample-127 blocked-scan combine (uniform execution)
    const float x27 = __shfl_sync(FULL, x, 27);   // S[0:112)
    const float x30 = __shfl_sync(FULL, x, 30);   // S[0:124)

    float r = 0.0f, g = 0.0f, b = 0.0f;
    render_step(run, sd0, c0.x, c0.y, c0.z, r, g, b);
    render_step(run, sd1, c0.w, c1.x, c1.y, r, g, b);
    render_step(run, sd2, c1.z, c1.w, c2.x, r, g, b);

    if (lane != 31) {
        render_step(run, sd3, c2.y, c2.z, c2.w, r, g, b);
    } else {
        // Blocked scan, chunk 16: local chunk covers samples [112,128).
        const float Lloc  = __fadd_rn(__fsub_rn(x30, x27),
                                      __fadd_rn(__fadd_rn(sd0, sd1), sd2));
        const float local = __fadd_rn(Lloc, sd3);
        const float cs    = __fadd_rn(x27, local);
        const float q     = __fsub_rn(cs, sd3);
        const float T     = expf(-q);
        const float w     = T * (1.0f - expf(-sd3));
        r += w * c2.y; g += w * c2.z; b += w * c2.w;
    }

    // warp reduction of RGB
    #pragma unroll
    for (int off = 16; off > 0; off >>= 1) {
        r += __shfl_xor_sync(FULL, r, off);
        g += __shfl_xor_sync(FULL, g, off);
        b += __shfl_xor_sync(FULL, b, off);
    }

    if (lane == 0) {
        const long long ob = (long long)ray * 3;
        out[ob + 0] = r;
        out[ob + 1] = g;
        out[ob + 2] = b;
    }
}

extern "C" void kernel_launch(void* const* d_in, const int* in_sizes, int n_in,
                              void* d_out, int out_size) {
    const float* dist  = (const float*)d_in[0];   // [M,128,1]
    const float* color = (const float*)d_in[1];   // [M,128,3]
    const float* depth = (const float*)d_in[2];   // [M,128]

    const int M = in_sizes[2] / 128;
    float* out = (float*)d_out;

    // Kernel writes out_color and geometry zeros; memset only any tail beyond.
    const long long expected = (long long)M * 6;
    if ((long long)out_size > expected) {
        cudaMemsetAsync(out + expected, 0,
                        ((long long)out_size - expected) * sizeof(float), 0);
    }

    const int threads = 512;              // 16 warps -> 16 rays per block
    const int blocks  = (M + 15) / 16;
    volsdf_render_kernel<<<blocks, threads>>>(dist, color, depth, out, M);
}